// round 5
// baseline (speedup 1.0000x reference)
#include <cuda_runtime.h>
#include <cstdint>
#include <cstddef>

// ---------------- problem dims ----------------
#define S_LEN  2048
#define BATCH  2
#define DMODEL 4096
#define NHQ    32
#define NKV    8
#define HDIM   128
#define N_QKV  ((NHQ + 2*NKV)*HDIM)   // 6144
#define MROWS  (S_LEN*BATCH)          // 4096
#define KG_ALL (DMODEL/8)             // 512

// ---------------- scratch (device globals; no allocs allowed) ----------------
// A-fragment layout: idx = ((mb*512 + kg)*32 + lane)*4 + v
__device__ float g_hid2 [(size_t)MROWS*DMODEL];
__device__ float g_attn2[(size_t)MROWS*DMODEL];
// W pair layout: idx = (kg*N + n)*8 + t2
__device__ float g_Wq2[(size_t)DMODEL*N_QKV];
__device__ float g_Wo2[(size_t)DMODEL*DMODEL];
// Q fragment layout: idx = (((bh*128 + sb)*16 + kk)*32 + lane)*4 + v
__device__ float g_Q2[(size_t)BATCH*NHQ*S_LEN*HDIM];
// K pair layout: idx = ((bhk*16 + ds)*2048 + s)*8 + t2   (pairs over d)
__device__ float g_K2[(size_t)BATCH*NKV*HDIM*S_LEN];
// V pair layout: idx = ((bhk*256 + kg)*128 + d)*8 + t2   (pairs over s)
__device__ float g_V2[(size_t)BATCH*NKV*S_LEN*HDIM];

// ---------------- small helpers ----------------
__device__ __forceinline__ uint32_t f2tf(float f) {
    uint32_t r; asm("cvt.rna.tf32.f32 %0, %1;" : "=r"(r) : "f"(f)); return r;
}
__device__ __forceinline__ float rtf(float f) { return __uint_as_float(f2tf(f)); }

__device__ __forceinline__ void mma_tf32(float* c, const uint32_t* a, const uint32_t* b) {
    asm volatile(
        "mma.sync.aligned.m16n8k8.row.col.f32.tf32.tf32.f32 "
        "{%0,%1,%2,%3},{%4,%5,%6,%7},{%8,%9},{%0,%1,%2,%3};"
        : "+f"(c[0]), "+f"(c[1]), "+f"(c[2]), "+f"(c[3])
        : "r"(a[0]), "r"(a[1]), "r"(a[2]), "r"(a[3]), "r"(b[0]), "r"(b[1]));
}
__device__ __forceinline__ void mma_b2(float* c, const uint32_t* a, float2 b) {
    uint32_t bb[2] = { __float_as_uint(b.x), __float_as_uint(b.y) };
    mma_tf32(c, a, bb);
}
__device__ __forceinline__ uint32_t s2u(const void* p) {
    return (uint32_t)__cvta_generic_to_shared(p);
}
__device__ __forceinline__ void cp16(uint32_t s, const void* g) {
    asm volatile("cp.async.cg.shared.global [%0], [%1], 16;" :: "r"(s), "l"(g));
}
__device__ __forceinline__ void cp_commit() { asm volatile("cp.async.commit_group;"); }
__device__ __forceinline__ void cp_wait0()  { asm volatile("cp.async.wait_group 0;"); }
__device__ __forceinline__ void cp_wait2()  { asm volatile("cp.async.wait_group 2;"); }

#define NEG_INF __int_as_float(0xff800000)

// =====================================================================
// Prepass 1: hidden [4096 x 4096] -> A-fragment layout (rounded)
// =====================================================================
__global__ __launch_bounds__(256) void pack_A_kernel(const float* __restrict__ src,
                                                     float* __restrict__ dst) {
    __shared__ float st[16][264];
    const int tid = threadIdx.x;
    const int mb = blockIdx.y;           // 256 blocks of 16 rows
    const int k0 = blockIdx.x * 256;     // 16 blocks of 256 cols
    #pragma unroll
    for (int p = 0; p < 16; p++) {
        int j = tid + p*256;
        int row = j >> 8, col = j & 255;
        st[row][col] = src[(size_t)(mb*16 + row)*DMODEL + k0 + col];
    }
    __syncthreads();
    const int kgb = k0 >> 3;
    #pragma unroll
    for (int p = 0; p < 4; p++) {
        int jb = tid + p*256;            // chunk (lane,v0..3): 1024 chunks
        int kg_l = jb >> 5, lane = jb & 31;
        int gid = lane >> 2, tig = lane & 3;
        float4 o;
        o.x = rtf(st[gid    ][kg_l*8 + tig    ]);
        o.y = rtf(st[gid + 8][kg_l*8 + tig    ]);
        o.z = rtf(st[gid    ][kg_l*8 + tig + 4]);
        o.w = rtf(st[gid + 8][kg_l*8 + tig + 4]);
        *(float4*)(dst + ((size_t)mb*512 + kgb + kg_l)*128 + lane*4) = o;
    }
}

// =====================================================================
// Prepass 2: W [4096 x N] -> pair layout [kg][n][8] (rounded)
// order within 8: position 2*j holds k=j, 2*j+1 holds k=j+4
// =====================================================================
template<int N>
__global__ __launch_bounds__(256) void pack_W_kernel(const float* __restrict__ src,
                                                     float* __restrict__ dst) {
    __shared__ float st[8][264];
    const int tid = threadIdx.x;
    const int kg = blockIdx.y;           // 512
    const int n0 = blockIdx.x * 256;
    #pragma unroll
    for (int p = 0; p < 8; p++)
        st[p][tid] = src[(size_t)(kg*8 + p)*N + n0 + tid];
    __syncthreads();
    const int n = n0 + tid;
    float4 lo, hi;
    lo.x = rtf(st[0][tid]); lo.y = rtf(st[4][tid]);
    lo.z = rtf(st[1][tid]); lo.w = rtf(st[5][tid]);
    hi.x = rtf(st[2][tid]); hi.y = rtf(st[6][tid]);
    hi.z = rtf(st[3][tid]); hi.w = rtf(st[7][tid]);
    float* d = dst + ((size_t)kg*N + n)*8;
    *(float4*)(d)     = lo;
    *(float4*)(d + 4) = hi;
}

// =====================================================================
// GEMM: C[M,N] = A2 * W2 (both pre-rounded, fragment layouts)
// CTA tile 128(M) x 256(N), warp tile 64x64, 8 warps (2x4),
// 4-stage cp.async pipeline (192 KB smem), k-tiles of 32.
// MODE 0: scatter epilogue -> g_Q2/g_K2/g_V2 (round; scale on Q)
// MODE 1: plain epilogue -> C fp32
// =====================================================================
#define STAGE_FLOATS 12288               // A 4096 + B 8192 floats (48 KB)
#define GEMM_SMEM (4*STAGE_FLOATS*4)     // 196608 B

__device__ __forceinline__ void qkv_store2(int r, int n, float val) {
    const int s = r >> 1, b = r & 1, d = n & 127;
    if (n < NHQ*HDIM) {
        const int h = n >> 7, bh = b*NHQ + h;
        const int sb = s >> 4, sl = s & 15, gq = sl & 7, rs = sl >> 3;
        const int kk = d >> 3, dl = d & 7, tq = dl & 3, cs = dl >> 2;
        const float scale = 0.08838834764831845f;  // 1/sqrt(128)
        g_Q2[((((size_t)bh*128 + sb)*16 + kk)*32 + gq*4 + tq)*4 + rs + 2*cs]
            = rtf(val * scale);
    } else if (n < (NHQ+NKV)*HDIM) {
        const int hk = (n - NHQ*HDIM) >> 7, bhk = b*NKV + hk;
        const int ds = d >> 3, dl = d & 7;
        const int t2 = (dl < 4) ? 2*dl : 2*(dl-4) + 1;
        g_K2[(((size_t)bhk*16 + ds)*S_LEN + s)*8 + t2] = rtf(val);
    } else {
        const int hk = (n - (NHQ+NKV)*HDIM) >> 7, bhk = b*NKV + hk;
        const int kg = s >> 3, sl = s & 7;
        const int t2 = (sl < 4) ? 2*sl : 2*(sl-4) + 1;
        g_V2[(((size_t)bhk*256 + kg)*HDIM + d)*8 + t2] = rtf(val);
    }
}

template<int N, int MODE>
__global__ __launch_bounds__(256, 1)
void gemm2_kernel(const float* __restrict__ A2,
                  const float* __restrict__ W2,
                  float* __restrict__ C) {
    constexpr int KT = DMODEL / 32;   // 128 k-tiles

    extern __shared__ float sm[];

    const int tid  = threadIdx.x;
    const int wid  = tid >> 5, lane = tid & 31;
    const int gid  = lane >> 2, tig = lane & 3;
    const int wrow = wid >> 2, wcol = wid & 3;   // warp grid 2(M) x 4(N)
    const int bn   = blockIdx.x, bm = blockIdx.y;

    // stage s: A frags at sm + s*12288 (mbl[8] x kgl[4] x lane[32] x v[4]),
    //          B pairs at sm + s*12288 + 4096 (kgl[4] x nl[256] x 8)
    auto load_stage = [&](int kt) {
        float* base = sm + (kt & 3)*STAGE_FLOATS;
        #pragma unroll
        for (int p = 0; p < 4; p++) {               // A: 1024 chunks
            int j = tid + p*256;
            int mbl = j >> 7, kgl = (j >> 5) & 3, ln = j & 31;
            cp16(s2u(base + j*4),
                 A2 + (((size_t)(bm*8 + mbl)*KG_ALL + kt*4 + kgl)*32 + ln)*4);
        }
        float* bb = base + 4096;
        #pragma unroll
        for (int p = 0; p < 8; p++) {               // B: 2048 chunks
            int j = tid + p*256;
            int kgl = j >> 9, r = j & 511, nl = r >> 1, half = r & 1;
            cp16(s2u(bb + kgl*2048 + nl*8 + half*4),
                 W2 + ((size_t)(kt*4 + kgl)*N + bn*256 + nl)*8 + half*4);
        }
        cp_commit();
    };

    float acc[4][8][4];
    #pragma unroll
    for (int mf = 0; mf < 4; mf++)
        #pragma unroll
        for (int nf = 0; nf < 8; nf++)
            #pragma unroll
            for (int i = 0; i < 4; i++) acc[mf][nf][i] = 0.f;

    load_stage(0);
    load_stage(1);
    load_stage(2);

    for (int kt = 0; kt < KT; kt++) {
        cp_wait2();          // stage kt landed (<=2 younger groups in flight)
        __syncthreads();     // all warps done with buffer (kt-1)&3
        if (kt + 3 < KT) load_stage(kt + 3);

        const float4* a4 = (const float4*)(sm + (kt & 3)*STAGE_FLOATS);
        const float2* b2 = (const float2*)(sm + (kt & 3)*STAGE_FLOATS + 4096);

        #pragma unroll
        for (int ks = 0; ks < 4; ks++) {
            uint32_t af[4][4];
            #pragma unroll
            for (int mf = 0; mf < 4; mf++) {
                float4 av = a4[((wrow*4 + mf)*4 + ks)*32 + lane];
                af[mf][0] = __float_as_uint(av.x);
                af[mf][1] = __float_as_uint(av.y);
                af[mf][2] = __float_as_uint(av.z);
                af[mf][3] = __float_as_uint(av.w);
            }
            #pragma unroll
            for (int nf = 0; nf < 8; nf++) {
                float2 bv = b2[(ks*256 + wcol*64 + nf*8 + gid)*4 + tig];
                #pragma unroll
                for (int mf = 0; mf < 4; mf++)
                    mma_b2(acc[mf][nf], af[mf], bv);
            }
        }
        __syncthreads();
    }

    // epilogue
    #pragma unroll
    for (int mf = 0; mf < 4; mf++) {
        #pragma unroll
        for (int nf = 0; nf < 8; nf++) {
            int r = bm*128 + wrow*64 + mf*16 + gid;
            int c = bn*256 + wcol*64 + nf*8 + tig*2;
            float v0 = acc[mf][nf][0], v1 = acc[mf][nf][1];
            float v2 = acc[mf][nf][2], v3 = acc[mf][nf][3];
            if (MODE == 1) {
                *(float2*)&C[(size_t)r*N + c]     = make_float2(v0, v1);
                *(float2*)&C[(size_t)(r+8)*N + c] = make_float2(v2, v3);
            } else {
                qkv_store2(r,   c,   v0);
                qkv_store2(r,   c+1, v1);
                qkv_store2(r+8, c,   v2);
                qkv_store2(r+8, c+1, v3);
            }
        }
    }
}

// =====================================================================
// Flash attention: block = (qtile 128, head h, batch b), 8 warps x 16 rows.
// K tile: [ds 16][kvl 64][8] pairs over d; V tile: [kgl 8][d 128][8] pairs over s.
// All operands pre-rounded tf32 -> zero cvt in loops; B frags are LDS.64.
// =====================================================================
#define BKV 64
#define ATTN_SMEM (2*(8192 + 8192)*4)   // 128 KB

__global__ __launch_bounds__(256, 1)
void attn_kernel() {
    extern __shared__ float sm[];
    float* Ks = sm;            // [2][8192]
    float* Vs = sm + 16384;    // [2][8192]

    const int tid = threadIdx.x;
    const int wid = tid >> 5, lane = tid & 31;
    const int gid = lane >> 2, tig = lane & 3;
    const int qt = blockIdx.x, h = blockIdx.y, b = blockIdx.z;
    const int hk = h >> 2;
    const int bh = b*NHQ + h, bhk = b*NKV + hk;

    // ---- Q fragments: 16 coalesced LDG.128 (pre-scaled, pre-rounded) ----
    const int sb = qt*8 + wid;
    const float4* q4 = (const float4*)g_Q2 + ((size_t)bh*128 + sb)*16*32 + lane;
    uint32_t qa[16][4];
    #pragma unroll
    for (int kk = 0; kk < 16; kk++) {
        float4 qv = q4[kk*32];
        qa[kk][0] = __float_as_uint(qv.x);
        qa[kk][1] = __float_as_uint(qv.y);
        qa[kk][2] = __float_as_uint(qv.z);
        qa[kk][3] = __float_as_uint(qv.w);
    }

    const float* Kg = g_K2 + (size_t)bhk*16*S_LEN*8;
    const float* Vg = g_V2 + (size_t)bhk*256*HDIM*8;

    auto loadKV = [&](int buf, int it) {
        float* kd = Ks + buf*8192;
        #pragma unroll
        for (int p = 0; p < 8; p++) {
            int j = tid + p*256;
            int ds = j >> 7, r = j & 127, kvl = r >> 1, half = r & 1;
            cp16(s2u(kd + ds*512 + kvl*8 + half*4),
                 Kg + ((size_t)ds*S_LEN + it*BKV + kvl)*8 + half*4);
        }
        float* vd = Vs + buf*8192;
        #pragma unroll
        for (int p = 0; p < 8; p++) {
            int j = tid + p*256;
            int kgl = j >> 8, r = j & 255, d = r >> 1, half = r & 1;
            cp16(s2u(vd + kgl*1024 + d*8 + half*4),
                 Vg + ((size_t)(it*8 + kgl)*HDIM + d)*8 + half*4);
        }
    };

    float m0 = NEG_INF, m1 = NEG_INF, l0 = 0.f, l1 = 0.f;
    float o[16][4];
    #pragma unroll
    for (int jn = 0; jn < 16; jn++)
        #pragma unroll
        for (int i = 0; i < 4; i++) o[jn][i] = 0.f;

    loadKV(0, 0); cp_commit();

    const int NIT = S_LEN / BKV;   // 32
    for (int it = 0; it < NIT; it++) {
        cp_wait0();
        __syncthreads();
        if (it + 1 < NIT) { loadKV((it+1)&1, it+1); cp_commit(); }

        const float2* kbuf = (const float2*)(Ks + (it&1)*8192);
        const float2* vbuf = (const float2*)(Vs + (it&1)*8192);

        // ---- S = Q K^T : 16 x 64 per warp ----
        float sc[8][4];
        #pragma unroll
        for (int jn = 0; jn < 8; jn++)
            #pragma unroll
            for (int i = 0; i < 4; i++) sc[jn][i] = 0.f;

        #pragma unroll
        for (int ks = 0; ks < 16; ks++) {
            #pragma unroll
            for (int jn = 0; jn < 8; jn++) {
                float2 kv = kbuf[(ks*64 + jn*8 + gid)*4 + tig];
                mma_b2(sc[jn], qa[ks], kv);
            }
        }

        // ---- online softmax ----
        float rmax0 = NEG_INF, rmax1 = NEG_INF;
        #pragma unroll
        for (int jn = 0; jn < 8; jn++) {
            rmax0 = fmaxf(rmax0, fmaxf(sc[jn][0], sc[jn][1]));
            rmax1 = fmaxf(rmax1, fmaxf(sc[jn][2], sc[jn][3]));
        }
        rmax0 = fmaxf(rmax0, __shfl_xor_sync(0xffffffffu, rmax0, 1));
        rmax0 = fmaxf(rmax0, __shfl_xor_sync(0xffffffffu, rmax0, 2));
        rmax1 = fmaxf(rmax1, __shfl_xor_sync(0xffffffffu, rmax1, 1));
        rmax1 = fmaxf(rmax1, __shfl_xor_sync(0xffffffffu, rmax1, 2));

        float mn0 = fmaxf(m0, rmax0), mn1 = fmaxf(m1, rmax1);
        float al0 = __expf(m0 - mn0), al1 = __expf(m1 - mn1);

        float rs0 = 0.f, rs1 = 0.f;
        #pragma unroll
        for (int jn = 0; jn < 8; jn++) {
            sc[jn][0] = rtf(__expf(sc[jn][0] - mn0));
            sc[jn][1] = rtf(__expf(sc[jn][1] - mn0));
            sc[jn][2] = rtf(__expf(sc[jn][2] - mn1));
            sc[jn][3] = rtf(__expf(sc[jn][3] - mn1));
            rs0 += sc[jn][0] + sc[jn][1];
            rs1 += sc[jn][2] + sc[jn][3];
        }
        rs0 += __shfl_xor_sync(0xffffffffu, rs0, 1);
        rs0 += __shfl_xor_sync(0xffffffffu, rs0, 2);
        rs1 += __shfl_xor_sync(0xffffffffu, rs1, 1);
        rs1 += __shfl_xor_sync(0xffffffffu, rs1, 2);

        l0 = l0*al0 + rs0;  l1 = l1*al1 + rs1;
        m0 = mn0;           m1 = mn1;

        #pragma unroll
        for (int jn = 0; jn < 16; jn++) {
            o[jn][0] *= al0; o[jn][1] *= al0;
            o[jn][2] *= al1; o[jn][3] *= al1;
        }

        // ---- O += P V : P C-layout -> A-layout via quad shuffles ----
        #pragma unroll
        for (int ks = 0; ks < 8; ks++) {
            int srcA = (lane & 28) + (tig >> 1);
            int srcB = srcA + 2;
            float xa0 = __shfl_sync(0xffffffffu, sc[ks][0], srcA);
            float ya0 = __shfl_sync(0xffffffffu, sc[ks][1], srcA);
            float xa2 = __shfl_sync(0xffffffffu, sc[ks][2], srcA);
            float ya2 = __shfl_sync(0xffffffffu, sc[ks][3], srcA);
            float xb0 = __shfl_sync(0xffffffffu, sc[ks][0], srcB);
            float yb0 = __shfl_sync(0xffffffffu, sc[ks][1], srcB);
            float xb2 = __shfl_sync(0xffffffffu, sc[ks][2], srcB);
            float yb2 = __shfl_sync(0xffffffffu, sc[ks][3], srcB);
            bool odd = (tig & 1);
            uint32_t pa[4];
            pa[0] = __float_as_uint(odd ? ya0 : xa0);   // (row gid,   k=tig)
            pa[1] = __float_as_uint(odd ? ya2 : xa2);   // (row gid+8, k=tig)
            pa[2] = __float_as_uint(odd ? yb0 : xb0);   // (row gid,   k=tig+4)
            pa[3] = __float_as_uint(odd ? yb2 : xb2);   // (row gid+8, k=tig+4)

            #pragma unroll
            for (int jn = 0; jn < 16; jn++) {
                float2 vv = vbuf[(ks*128 + jn*8 + gid)*4 + tig];
                mma_b2(o[jn], pa, vv);
            }
        }
    }

    // ---- epilogue: scatter (rounded) into g_attn2 A-fragment layout ----
    float il0 = 1.f / l0, il1 = 1.f / l1;
    const int s0 = qt*128 + wid*16 + gid;
    #pragma unroll
    for (int jn = 0; jn < 16; jn++) {
        int c0 = h*HDIM + jn*8 + tig*2;
        float vals[4] = { o[jn][0]*il0, o[jn][1]*il0, o[jn][2]*il1, o[jn][3]*il1 };
        #pragma unroll
        for (int i = 0; i < 4; i++) {
            int s = s0 + (i >> 1)*8;
            int k = c0 + (i & 1);
            int m = 2*s + b;
            int mb = m >> 4, ml = m & 15, gA = ml & 7, rs = ml >> 3;
            int kg = k >> 3, kl = k & 7, tA = kl & 3, cs = kl >> 2;
            g_attn2[(((size_t)mb*KG_ALL + kg)*32 + gA*4 + tA)*4 + rs + 2*cs]
                = rtf(vals[i]);
        }
    }
}

// =====================================================================
// launcher
// =====================================================================
extern "C" void kernel_launch(void* const* d_in, const int* in_sizes, int n_in,
                              void* d_out, int out_size) {
    const float* hidden = (const float*)d_in[0];
    const float* w_qkv  = (const float*)d_in[1];
    const float* w_o    = (const float*)d_in[2];
    float* out = (float*)d_out;

    cudaFuncSetAttribute(gemm2_kernel<N_QKV,0>,
                         cudaFuncAttributeMaxDynamicSharedMemorySize, GEMM_SMEM);
    cudaFuncSetAttribute(gemm2_kernel<DMODEL,1>,
                         cudaFuncAttributeMaxDynamicSharedMemorySize, GEMM_SMEM);
    cudaFuncSetAttribute(attn_kernel,
                         cudaFuncAttributeMaxDynamicSharedMemorySize, ATTN_SMEM);

    float* hid2;  cudaGetSymbolAddress((void**)&hid2,  g_hid2);
    float* wq2;   cudaGetSymbolAddress((void**)&wq2,   g_Wq2);
    float* wo2;   cudaGetSymbolAddress((void**)&wo2,   g_Wo2);
    float* at2;   cudaGetSymbolAddress((void**)&at2,   g_attn2);

    // 0) prepasses: round-to-tf32 + permute into fragment-native layouts
    pack_A_kernel<<<dim3(16, 256), 256>>>(hidden, hid2);
    pack_W_kernel<N_QKV><<<dim3(N_QKV/256, KG_ALL), 256>>>(w_qkv, wq2);
    pack_W_kernel<DMODEL><<<dim3(DMODEL/256, KG_ALL), 256>>>(w_o, wo2);

    // 1) fused QKV projection, scatter epilogue -> Q2/K2/V2
    gemm2_kernel<N_QKV,0><<<dim3(N_QKV/256, MROWS/128), 256, GEMM_SMEM>>>(hid2, wq2, nullptr);

    // 2) flash attention (full softmax == ring online-softmax)
    attn_kernel<<<dim3(S_LEN/128, NHQ, BATCH), 256, ATTN_SMEM>>>();

    // 3) output projection
    gemm2_kernel<DMODEL,1><<<dim3(DMODEL/256, MROWS/128), 256, GEMM_SMEM>>>(at2, wo2, out);
}

// round 6
// speedup vs baseline: 2.0688x; 2.0688x over previous
#include <cuda_runtime.h>
#include <cuda_fp16.h>
#include <cstdint>
#include <cstddef>

// ---------------- problem dims ----------------
#define S_LEN  2048
#define BATCH  2
#define DMODEL 4096
#define NHQ    32
#define NKV    8
#define HDIM   128
#define N_QKV  ((NHQ + 2*NKV)*HDIM)   // 6144
#define MROWS  (S_LEN*BATCH)          // 4096
#define KG16   (DMODEL/16)            // 256

// ---------------- scratch (device globals) ----------------
// A-fragment half layout: ((mb*KG16 + kg)*32 + lane)*8 + (rs+2cs)*2 + lo
__device__ __half g_hid2h [(size_t)MROWS*DMODEL];
__device__ __half g_attn2h[(size_t)MROWS*DMODEL];
// W pair half layout: (kg*N + n)*16 + t2*2 + lo
__device__ __half g_Wq2h[(size_t)DMODEL*N_QKV];
__device__ __half g_Wo2h[(size_t)DMODEL*DMODEL];
// Q A-frag layout: (((bh*128+sb)*8 + kk)*32 + lane)*8 + (rs+2cs)*2 + lo
__device__ __half g_Q2h[(size_t)BATCH*NHQ*S_LEN*HDIM];
// K pair layout (pairs over d):  ((bhk*8+ds)*2048 + s)*16 + t2*2 + lo
__device__ __half g_K2h[(size_t)BATCH*NKV*S_LEN*HDIM];
// V pair layout (pairs over s):  ((bhk*128+kg)*128 + d)*16 + t2*2 + lo
__device__ __half g_V2h[(size_t)BATCH*NKV*S_LEN*HDIM];

// ---------------- helpers ----------------
__device__ __forceinline__ uint32_t f2h2(float lo, float hi) {
    __half2 h = __floats2half2_rn(lo, hi);   // .x = lo half
    return *reinterpret_cast<uint32_t*>(&h);
}
__device__ __forceinline__ void mma_f16(float* c, const uint32_t* a, const uint32_t* b) {
    asm volatile(
        "mma.sync.aligned.m16n8k16.row.col.f32.f16.f16.f32 "
        "{%0,%1,%2,%3},{%4,%5,%6,%7},{%8,%9},{%0,%1,%2,%3};"
        : "+f"(c[0]), "+f"(c[1]), "+f"(c[2]), "+f"(c[3])
        : "r"(a[0]), "r"(a[1]), "r"(a[2]), "r"(a[3]), "r"(b[0]), "r"(b[1]));
}
__device__ __forceinline__ uint32_t s2u(const void* p) {
    return (uint32_t)__cvta_generic_to_shared(p);
}
__device__ __forceinline__ void cp16(uint32_t s, const void* g) {
    asm volatile("cp.async.cg.shared.global [%0], [%1], 16;" :: "r"(s), "l"(g));
}
__device__ __forceinline__ void cp_commit() { asm volatile("cp.async.commit_group;"); }
__device__ __forceinline__ void cp_wait0() { asm volatile("cp.async.wait_group 0;"); }
__device__ __forceinline__ void cp_wait1() { asm volatile("cp.async.wait_group 1;"); }
__device__ __forceinline__ void cp_wait2() { asm volatile("cp.async.wait_group 2;"); }

#define NEG_INF __int_as_float(0xff800000)

// =====================================================================
// Prepass 1: hidden [4096 x 4096] fp32 -> A-fragment fp16 layout
// =====================================================================
__global__ __launch_bounds__(256) void pack_A_kernel(const float* __restrict__ src,
                                                     __half* __restrict__ dst) {
    __shared__ float st[16][264];
    const int tid = threadIdx.x;
    const int mb = blockIdx.y;           // 256 blocks of 16 rows
    const int k0 = blockIdx.x * 256;     // 16 blocks of 256 cols
    #pragma unroll
    for (int p = 0; p < 16; p++) {
        int j = tid + p*256;
        int row = j >> 8, col = j & 255;
        st[row][col] = src[(size_t)(mb*16 + row)*DMODEL + k0 + col];
    }
    __syncthreads();
    const int kgb = k0 >> 4;             // 16 kg groups per block
    #pragma unroll
    for (int p = 0; p < 2; p++) {
        int jb = tid + p*256;            // 0..511 chunks (kg_l, lane)
        int kg_l = jb >> 5, lane = jb & 31;
        int gid = lane >> 2, tq = lane & 3;
        int c0 = kg_l*16 + 2*tq;
        int c1 = c0 + 8;
        uint4 o;
        o.x = f2h2(st[gid    ][c0], st[gid    ][c0+1]);   // v0: rs0 cs0
        o.y = f2h2(st[gid + 8][c0], st[gid + 8][c0+1]);   // v1: rs1 cs0
        o.z = f2h2(st[gid    ][c1], st[gid    ][c1+1]);   // v2: rs0 cs1
        o.w = f2h2(st[gid + 8][c1], st[gid + 8][c1+1]);   // v3: rs1 cs1
        *(uint4*)(dst + (((size_t)mb*KG16 + kgb + kg_l)*32 + lane)*8) = o;
    }
}

// =====================================================================
// Prepass 2: W [4096 x N] fp32 -> pair fp16 layout [kg16][n][16]
// half2 j={k=2j,2j+1}, interleaved positions t2: [0,4,1,5,2,6,3,7]
// =====================================================================
template<int N>
__global__ __launch_bounds__(256) void pack_W_kernel(const float* __restrict__ src,
                                                     __half* __restrict__ dst) {
    __shared__ float st[16][264];
    const int tid = threadIdx.x;
    const int kg = blockIdx.y;           // 256 kg groups
    const int n0 = blockIdx.x * 256;
    #pragma unroll
    for (int p = 0; p < 16; p++)
        st[p][tid] = src[(size_t)(kg*16 + p)*N + n0 + tid];
    __syncthreads();
    const int n = n0 + tid;
    uint32_t h2s[8];
    #pragma unroll
    for (int j = 0; j < 8; j++) {
        int t2 = (j < 4) ? 2*j : 2*(j-4) + 1;
        h2s[t2] = f2h2(st[2*j][tid], st[2*j+1][tid]);
    }
    uint4* d = (uint4*)(dst + ((size_t)kg*N + n)*16);
    d[0] = make_uint4(h2s[0], h2s[1], h2s[2], h2s[3]);
    d[1] = make_uint4(h2s[4], h2s[5], h2s[6], h2s[7]);
}

// =====================================================================
// fp16 GEMM: C[M,N] = A * W, CTA 128x128, warp tile 32x64 (8 warps 4x2),
// BK=64 (4 k-groups of 16), 3-stage cp.async pipeline, 2 CTAs/SM.
// MODE 0: scatter epilogue -> Q2h/K2h/V2h;  MODE 1: fp32 C out.
// =====================================================================
#define GSTAGE_HALF 16384                 // A 8192 + B 8192 halves (32 KB)
#define GEMM_SMEM (3*GSTAGE_HALF*2)       // 98304 B

__device__ __forceinline__ void qkv_store_h(int r, int n, float val) {
    const int s = r >> 1, b = r & 1, d = n & 127;
    if (n < NHQ*HDIM) {
        const int h = n >> 7, bh = b*NHQ + h;
        const int sb = s >> 4, sl = s & 15, gq = sl & 7, rs = sl >> 3;
        const int kk = d >> 4, dl = d & 15, cs = dl >> 3, tq = (dl & 7) >> 1, lo = d & 1;
        const float scale = 0.08838834764831845f;  // 1/sqrt(128)
        g_Q2h[((((size_t)bh*128 + sb)*8 + kk)*32 + gq*4 + tq)*8 + (rs + 2*cs)*2 + lo]
            = __float2half_rn(val * scale);
    } else if (n < (NHQ+NKV)*HDIM) {
        const int hk = (n - NHQ*HDIM) >> 7, bhk = b*NKV + hk;
        const int ds = d >> 4, dl = d & 15, j = dl >> 1, lo = d & 1;
        const int t2 = (j < 4) ? 2*j : 2*(j-4) + 1;
        g_K2h[(((size_t)bhk*8 + ds)*S_LEN + s)*16 + t2*2 + lo] = __float2half_rn(val);
    } else {
        const int hk = (n - (NHQ+NKV)*HDIM) >> 7, bhk = b*NKV + hk;
        const int kg = s >> 4, sl = s & 15, j = sl >> 1, lo = s & 1;
        const int t2 = (j < 4) ? 2*j : 2*(j-4) + 1;
        g_V2h[(((size_t)bhk*128 + kg)*128 + d)*16 + t2*2 + lo] = __float2half_rn(val);
    }
}

template<int N, int MODE>
__global__ __launch_bounds__(256, 2)
void gemm_h_kernel(const __half* __restrict__ Ah,
                   const __half* __restrict__ Wh,
                   float* __restrict__ C) {
    constexpr int KT = DMODEL / 64;   // 64 k-tiles

    extern __shared__ __half sh[];

    const int tid  = threadIdx.x;
    const int wid  = tid >> 5, lane = tid & 31;
    const int gid  = lane >> 2, tig = lane & 3;
    const int wrow = wid >> 1, wcol = wid & 1;   // warp grid 4(M) x 2(N)
    const int bn   = blockIdx.x, bm = blockIdx.y;

    // stage: A halves [mbl 8][kgl 4][lane 32][8]  then B [kgl 4][nl 128][16]
    auto load_stage = [&](int kt) {
        __half* base = sh + (kt % 3)*GSTAGE_HALF;
        #pragma unroll
        for (int p = 0; p < 4; p++) {            // A: 1024 16B-chunks
            int j = tid + p*256;
            int mbl = j >> 7, kgl = (j >> 5) & 3, ln = j & 31;
            cp16(s2u(base + (size_t)j*8),
                 Ah + (((size_t)(bm*8 + mbl)*KG16 + kt*4 + kgl)*32 + ln)*8);
        }
        __half* bb = base + 8192;
        #pragma unroll
        for (int p = 0; p < 4; p++) {            // B: 1024 16B-chunks
            int j = tid + p*256;
            int kgl = j >> 8, r = j & 255, nl = r >> 1, hf = r & 1;
            cp16(s2u(bb + (kgl*128 + nl)*16 + hf*8),
                 Wh + ((size_t)(kt*4 + kgl)*N + bn*128 + nl)*16 + hf*8);
        }
        cp_commit();
    };

    float acc[2][8][4];
    #pragma unroll
    for (int mf = 0; mf < 2; mf++)
        #pragma unroll
        for (int nf = 0; nf < 8; nf++)
            #pragma unroll
            for (int i = 0; i < 4; i++) acc[mf][nf][i] = 0.f;

    load_stage(0);
    load_stage(1);

    for (int kt = 0; kt < KT; kt++) {
        if (kt + 2 < KT) cp_wait1(); else cp_wait0();
        __syncthreads();
        if (kt + 2 < KT) load_stage(kt + 2);

        const __half* base = sh + (kt % 3)*GSTAGE_HALF;
        const uint4* a4 = (const uint4*)base;
        const uint2* b2 = (const uint2*)(base + 8192);

        #pragma unroll
        for (int ks = 0; ks < 4; ks++) {
            uint32_t af[2][4];
            #pragma unroll
            for (int mf = 0; mf < 2; mf++) {
                uint4 av = a4[((wrow*2 + mf)*4 + ks)*32 + lane];
                af[mf][0] = av.x; af[mf][1] = av.y;
                af[mf][2] = av.z; af[mf][3] = av.w;
            }
            #pragma unroll
            for (int nf = 0; nf < 8; nf++) {
                uint2 bv = b2[(ks*128 + wcol*64 + nf*8 + gid)*4 + tig];
                mma_f16(acc[0][nf], af[0], (const uint32_t*)&bv);
                mma_f16(acc[1][nf], af[1], (const uint32_t*)&bv);
            }
        }
    }

    // epilogue
    #pragma unroll
    for (int mf = 0; mf < 2; mf++) {
        #pragma unroll
        for (int nf = 0; nf < 8; nf++) {
            int r = bm*128 + wrow*32 + mf*16 + gid;
            int c = bn*128 + wcol*64 + nf*8 + tig*2;
            float v0 = acc[mf][nf][0], v1 = acc[mf][nf][1];
            float v2 = acc[mf][nf][2], v3 = acc[mf][nf][3];
            if (MODE == 1) {
                *(float2*)&C[(size_t)r*N + c]     = make_float2(v0, v1);
                *(float2*)&C[(size_t)(r+8)*N + c] = make_float2(v2, v3);
            } else {
                qkv_store_h(r,   c,   v0);
                qkv_store_h(r,   c+1, v1);
                qkv_store_h(r+8, c,   v2);
                qkv_store_h(r+8, c+1, v3);
            }
        }
    }
}

// =====================================================================
// fp16 flash attention: block = (qtile 128, head h, batch b),
// 8 warps x 16 q-rows, BKV=64, 4-stage cp.async pipeline.
// K tile [ds 8][kvl 64][16]; V tile [kg 4][d 128][16]  (32 KB/stage)
// =====================================================================
#define ASTAGE_HALF 16384
#define ATTN_SMEM (4*ASTAGE_HALF*2)   // 131072 B

__global__ __launch_bounds__(256, 1)
void attn_kernel() {
    extern __shared__ __half sh[];

    const int tid = threadIdx.x;
    const int wid = tid >> 5, lane = tid & 31;
    const int gid = lane >> 2, tig = lane & 3;
    const int qt = blockIdx.x, h = blockIdx.y, b = blockIdx.z;
    const int hk = h >> 2;
    const int bh = b*NHQ + h, bhk = b*NKV + hk;

    // ---- Q fragments: 8 coalesced LDG.128 (pre-scaled fp16) ----
    const int sb = qt*8 + wid;
    const uint4* q4 = (const uint4*)g_Q2h + ((size_t)bh*128 + sb)*8*32 + lane;
    uint32_t qa[8][4];
    #pragma unroll
    for (int kk = 0; kk < 8; kk++) {
        uint4 qv = q4[kk*32];
        qa[kk][0] = qv.x; qa[kk][1] = qv.y; qa[kk][2] = qv.z; qa[kk][3] = qv.w;
    }

    const __half* Kg = g_K2h + (size_t)bhk*8*S_LEN*16;
    const __half* Vg = g_V2h + (size_t)bhk*128*HDIM*16;

    auto loadKV = [&](int it) {
        __half* kd = sh + (it & 3)*ASTAGE_HALF;
        #pragma unroll
        for (int p = 0; p < 4; p++) {            // K: 1024 chunks
            int j = tid + p*256;
            int ds = j >> 7, r = j & 127, kvl = r >> 1, hf = r & 1;
            cp16(s2u(kd + (ds*64 + kvl)*16 + hf*8),
                 Kg + ((size_t)ds*S_LEN + it*64 + kvl)*16 + hf*8);
        }
        __half* vd = kd + 8192;
        #pragma unroll
        for (int p = 0; p < 4; p++) {            // V: 1024 chunks
            int j = tid + p*256;
            int kg = j >> 8, r = j & 255, d = r >> 1, hf = r & 1;
            cp16(s2u(vd + (kg*128 + d)*16 + hf*8),
                 Vg + ((size_t)(it*4 + kg)*HDIM + d)*16 + hf*8);
        }
        cp_commit();
    };

    float m0 = NEG_INF, m1 = NEG_INF, l0 = 0.f, l1 = 0.f;
    float o[16][4];
    #pragma unroll
    for (int jn = 0; jn < 16; jn++)
        #pragma unroll
        for (int i = 0; i < 4; i++) o[jn][i] = 0.f;

    loadKV(0); loadKV(1); loadKV(2);

    const int NIT = S_LEN / 64;   // 32
    for (int it = 0; it < NIT; it++) {
        if (it + 3 < NIT) cp_wait2(); else cp_wait0();
        __syncthreads();
        if (it + 3 < NIT) loadKV(it + 3);

        const __half* base = sh + (it & 3)*ASTAGE_HALF;
        const uint2* kb = (const uint2*)base;
        const uint2* vb = (const uint2*)(base + 8192);

        // ---- S = Q K^T : 16 x 64 per warp (8 ks x 8 jn MMAs) ----
        float sc[8][4];
        #pragma unroll
        for (int jn = 0; jn < 8; jn++)
            #pragma unroll
            for (int i = 0; i < 4; i++) sc[jn][i] = 0.f;

        #pragma unroll
        for (int ks = 0; ks < 8; ks++) {
            #pragma unroll
            for (int jn = 0; jn < 8; jn++) {
                uint2 kv = kb[(ks*64 + jn*8 + gid)*4 + tig];
                mma_f16(sc[jn], qa[ks], (const uint32_t*)&kv);
            }
        }

        // ---- online softmax (rows gid, gid+8; quad reductions) ----
        float rmax0 = NEG_INF, rmax1 = NEG_INF;
        #pragma unroll
        for (int jn = 0; jn < 8; jn++) {
            rmax0 = fmaxf(rmax0, fmaxf(sc[jn][0], sc[jn][1]));
            rmax1 = fmaxf(rmax1, fmaxf(sc[jn][2], sc[jn][3]));
        }
        rmax0 = fmaxf(rmax0, __shfl_xor_sync(0xffffffffu, rmax0, 1));
        rmax0 = fmaxf(rmax0, __shfl_xor_sync(0xffffffffu, rmax0, 2));
        rmax1 = fmaxf(rmax1, __shfl_xor_sync(0xffffffffu, rmax1, 1));
        rmax1 = fmaxf(rmax1, __shfl_xor_sync(0xffffffffu, rmax1, 2));

        float mn0 = fmaxf(m0, rmax0), mn1 = fmaxf(m1, rmax1);
        float al0 = __expf(m0 - mn0), al1 = __expf(m1 - mn1);

        float rs0 = 0.f, rs1 = 0.f;
        #pragma unroll
        for (int jn = 0; jn < 8; jn++) {
            sc[jn][0] = __expf(sc[jn][0] - mn0);
            sc[jn][1] = __expf(sc[jn][1] - mn0);
            sc[jn][2] = __expf(sc[jn][2] - mn1);
            sc[jn][3] = __expf(sc[jn][3] - mn1);
            rs0 += sc[jn][0] + sc[jn][1];
            rs1 += sc[jn][2] + sc[jn][3];
        }
        rs0 += __shfl_xor_sync(0xffffffffu, rs0, 1);
        rs0 += __shfl_xor_sync(0xffffffffu, rs0, 2);
        rs1 += __shfl_xor_sync(0xffffffffu, rs1, 1);
        rs1 += __shfl_xor_sync(0xffffffffu, rs1, 2);

        l0 = l0*al0 + rs0;  l1 = l1*al1 + rs1;
        m0 = mn0;           m1 = mn1;

        #pragma unroll
        for (int jn = 0; jn < 16; jn++) {
            o[jn][0] *= al0; o[jn][1] *= al0;
            o[jn][2] *= al1; o[jn][3] *= al1;
        }

        // ---- O += P V : C-frag of S == A-frag halves of P (no shuffles) ----
        #pragma unroll
        for (int g = 0; g < 4; g++) {
            uint32_t pa[4];
            pa[0] = f2h2(sc[2*g  ][0], sc[2*g  ][1]);   // row gid,   kv 2tig..+1
            pa[1] = f2h2(sc[2*g  ][2], sc[2*g  ][3]);   // row gid+8
            pa[2] = f2h2(sc[2*g+1][0], sc[2*g+1][1]);   // row gid,   kv +8
            pa[3] = f2h2(sc[2*g+1][2], sc[2*g+1][3]);   // row gid+8
            #pragma unroll
            for (int jn = 0; jn < 16; jn++) {
                uint2 vv = vb[(g*128 + jn*8 + gid)*4 + tig];
                mma_f16(o[jn], pa, (const uint32_t*)&vv);
            }
        }
    }

    // ---- epilogue: fp16 A-fragment scatter into g_attn2h ----
    float il0 = 1.f / l0, il1 = 1.f / l1;
    const int s0 = qt*128 + wid*16 + gid;
    #pragma unroll
    for (int jn = 0; jn < 16; jn++) {
        int c0 = h*HDIM + jn*8 + tig*2;
        float vals[4] = { o[jn][0]*il0, o[jn][1]*il0, o[jn][2]*il1, o[jn][3]*il1 };
        #pragma unroll
        for (int i = 0; i < 4; i++) {
            int s = s0 + (i & 1)*8;          // c0,c1 row gid; c2,c3 row gid+8
            int k = c0 + (i >> 1);
            // careful: i=0,1 -> cols c0,c0+1 row gid ; i=2,3 -> row gid+8
            ;
        }
        // explicit mapping (c-layout): [0]=(gid,c0) [1]=(gid,c0+1) [2]=(gid+8,c0) [3]=(gid+8,c0+1)
        #pragma unroll
        for (int i = 0; i < 4; i++) {
            int s = s0 + (i >> 1)*8;
            int k = c0 + (i & 1);
            int m = 2*s + b;
            int mb = m >> 4, ml = m & 15, gA = ml & 7, rsA = ml >> 3;
            int kg = k >> 4, kl = k & 15, csA = kl >> 3, tA = (kl & 7) >> 1, loA = k & 1;
            g_attn2h[(((size_t)mb*KG16 + kg)*32 + gA*4 + tA)*8 + (rsA + 2*csA)*2 + loA]
                = __float2half_rn(vals[i]);
        }
    }
}

// =====================================================================
// launcher
// =====================================================================
extern "C" void kernel_launch(void* const* d_in, const int* in_sizes, int n_in,
                              void* d_out, int out_size) {
    const float* hidden = (const float*)d_in[0];
    const float* w_qkv  = (const float*)d_in[1];
    const float* w_o    = (const float*)d_in[2];
    float* out = (float*)d_out;

    cudaFuncSetAttribute(gemm_h_kernel<N_QKV,0>,
                         cudaFuncAttributeMaxDynamicSharedMemorySize, GEMM_SMEM);
    cudaFuncSetAttribute(gemm_h_kernel<DMODEL,1>,
                         cudaFuncAttributeMaxDynamicSharedMemorySize, GEMM_SMEM);
    cudaFuncSetAttribute(attn_kernel,
                         cudaFuncAttributeMaxDynamicSharedMemorySize, ATTN_SMEM);

    __half* hid2h;  cudaGetSymbolAddress((void**)&hid2h, g_hid2h);
    __half* wq2h;   cudaGetSymbolAddress((void**)&wq2h,  g_Wq2h);
    __half* wo2h;   cudaGetSymbolAddress((void**)&wo2h,  g_Wo2h);
    __half* at2h;   cudaGetSymbolAddress((void**)&at2h,  g_attn2h);

    // 0) prepasses: fp32 -> fp16 fragment/pair layouts
    pack_A_kernel<<<dim3(16, 256), 256>>>(hidden, hid2h);
    pack_W_kernel<N_QKV><<<dim3(N_QKV/256, KG16), 256>>>(w_qkv, wq2h);
    pack_W_kernel<DMODEL><<<dim3(DMODEL/256, KG16), 256>>>(w_o, wo2h);

    // 1) fused QKV projection, scatter epilogue -> Q2h/K2h/V2h
    gemm_h_kernel<N_QKV,0><<<dim3(N_QKV/128, MROWS/128), 256, GEMM_SMEM>>>(hid2h, wq2h, nullptr);

    // 2) flash attention (full softmax == ring online-softmax)
    attn_kernel<<<dim3(S_LEN/128, NHQ, BATCH), 256, ATTN_SMEM>>>();

    // 3) output projection
    gemm_h_kernel<DMODEL,1><<<dim3(DMODEL/128, MROWS/128), 256, GEMM_SMEM>>>(at2h, wo2h, out);
}

// round 7
// speedup vs baseline: 2.1135x; 1.0216x over previous
#include <cuda_runtime.h>
#include <cuda_fp16.h>
#include <cstdint>
#include <cstddef>

// ---------------- problem dims ----------------
#define S_LEN  2048
#define BATCH  2
#define DMODEL 4096
#define NHQ    32
#define NKV    8
#define HDIM   128
#define N_QKV  ((NHQ + 2*NKV)*HDIM)   // 6144
#define MROWS  (S_LEN*BATCH)          // 4096
#define KG16   (DMODEL/16)            // 256
#define NSM    148
#define GRID_P (2*NSM)                // persistent grid

// ---------------- scratch (device globals) ----------------
__device__ __half g_hid2h [(size_t)MROWS*DMODEL];
__device__ __half g_attn2h[(size_t)MROWS*DMODEL];
__device__ __half g_Wq2h[(size_t)DMODEL*N_QKV];
__device__ __half g_Wo2h[(size_t)DMODEL*DMODEL];
// Q A-frag layout: (((bh*128+sb)*8 + kk)*32 + lane)*8 + (rs+2cs)*2 + lo
__device__ __half g_Q2h[(size_t)BATCH*NHQ*S_LEN*HDIM];
// K pair layout (pairs over d):  ((bhk*8+ds)*2048 + s)*16 + t2*2 + lo
__device__ __half g_K2h[(size_t)BATCH*NKV*S_LEN*HDIM];
// V pair layout (pairs over s):  ((bhk*128+kg)*128 + d)*16 + t2*2 + lo
__device__ __half g_V2h[(size_t)BATCH*NKV*S_LEN*HDIM];

// ---------------- helpers ----------------
__device__ __forceinline__ uint32_t f2h2(float lo, float hi) {
    __half2 h = __floats2half2_rn(lo, hi);   // .x = lo half
    return *reinterpret_cast<uint32_t*>(&h);
}
__device__ __forceinline__ void mma_f16(float* c, const uint32_t* a, const uint32_t* b) {
    asm volatile(
        "mma.sync.aligned.m16n8k16.row.col.f32.f16.f16.f32 "
        "{%0,%1,%2,%3},{%4,%5,%6,%7},{%8,%9},{%0,%1,%2,%3};"
        : "+f"(c[0]), "+f"(c[1]), "+f"(c[2]), "+f"(c[3])
        : "r"(a[0]), "r"(a[1]), "r"(a[2]), "r"(a[3]), "r"(b[0]), "r"(b[1]));
}
__device__ __forceinline__ uint32_t s2u(const void* p) {
    return (uint32_t)__cvta_generic_to_shared(p);
}
__device__ __forceinline__ void cp16(uint32_t s, const void* g) {
    asm volatile("cp.async.cg.shared.global [%0], [%1], 16;" :: "r"(s), "l"(g));
}
__device__ __forceinline__ void cp_commit() { asm volatile("cp.async.commit_group;"); }
__device__ __forceinline__ void cp_wait0() { asm volatile("cp.async.wait_group 0;"); }
__device__ __forceinline__ void cp_wait1() { asm volatile("cp.async.wait_group 1;"); }
__device__ __forceinline__ void cp_wait2() { asm volatile("cp.async.wait_group 2;"); }

#define NEG_INF __int_as_float(0xff800000)

// =====================================================================
// Prepass 1: hidden [4096 x 4096] fp32 -> A-fragment fp16 layout
// =====================================================================
__global__ __launch_bounds__(256) void pack_A_kernel(const float* __restrict__ src,
                                                     __half* __restrict__ dst) {
    __shared__ float st[16][264];
    const int tid = threadIdx.x;
    const int mb = blockIdx.y;
    const int k0 = blockIdx.x * 256;
    #pragma unroll
    for (int p = 0; p < 16; p++) {
        int j = tid + p*256;
        int row = j >> 8, col = j & 255;
        st[row][col] = src[(size_t)(mb*16 + row)*DMODEL + k0 + col];
    }
    __syncthreads();
    const int kgb = k0 >> 4;
    #pragma unroll
    for (int p = 0; p < 2; p++) {
        int jb = tid + p*256;
        int kg_l = jb >> 5, lane = jb & 31;
        int gid = lane >> 2, tq = lane & 3;
        int c0 = kg_l*16 + 2*tq;
        int c1 = c0 + 8;
        uint4 o;
        o.x = f2h2(st[gid    ][c0], st[gid    ][c0+1]);
        o.y = f2h2(st[gid + 8][c0], st[gid + 8][c0+1]);
        o.z = f2h2(st[gid    ][c1], st[gid    ][c1+1]);
        o.w = f2h2(st[gid + 8][c1], st[gid + 8][c1+1]);
        *(uint4*)(dst + (((size_t)mb*KG16 + kgb + kg_l)*32 + lane)*8) = o;
    }
}

// =====================================================================
// Prepass 2: W [4096 x N] fp32 -> pair fp16 layout [kg16][n][16]
// =====================================================================
template<int N>
__global__ __launch_bounds__(256) void pack_W_kernel(const float* __restrict__ src,
                                                     __half* __restrict__ dst) {
    __shared__ float st[16][264];
    const int tid = threadIdx.x;
    const int kg = blockIdx.y;
    const int n0 = blockIdx.x * 256;
    #pragma unroll
    for (int p = 0; p < 16; p++)
        st[p][tid] = src[(size_t)(kg*16 + p)*N + n0 + tid];
    __syncthreads();
    const int n = n0 + tid;
    uint32_t h2s[8];
    #pragma unroll
    for (int j = 0; j < 8; j++) {
        int t2 = (j < 4) ? 2*j : 2*(j-4) + 1;
        h2s[t2] = f2h2(st[2*j][tid], st[2*j+1][tid]);
    }
    uint4* d = (uint4*)(dst + ((size_t)kg*N + n)*16);
    d[0] = make_uint4(h2s[0], h2s[1], h2s[2], h2s[3]);
    d[1] = make_uint4(h2s[4], h2s[5], h2s[6], h2s[7]);
}

// =====================================================================
// fp16 GEMM, persistent CTAs. CTA tile 128x128, warp 32x64 (4Mx2N),
// BK=64, 3-stage cp.async, 2 CTAs/SM.
// MODE 0: smem-staged coalesced scatter -> Q2h/K2h/V2h
// MODE 1: fp32 row-major C
// =====================================================================
#define GSTAGE_HALF 16384                 // 32 KB per stage
#define GEMM_SMEM (3*GSTAGE_HALF*2)       // 98304 B
#define SROW 136                          // staging row stride in halves

template<int N, int MODE>
__global__ __launch_bounds__(256, 2)
void gemm_h_kernel(const __half* __restrict__ Ah,
                   const __half* __restrict__ Wh,
                   float* __restrict__ C) {
    constexpr int KT  = DMODEL / 64;     // 64
    constexpr int NBN = N / 128;
    constexpr int NT  = (MROWS/128) * NBN;

    extern __shared__ __half sh[];

    const int tid  = threadIdx.x;
    const int wid  = tid >> 5, lane = tid & 31;
    const int gid  = lane >> 2, tig = lane & 3;
    const int wrow = wid >> 1, wcol = wid & 1;

    for (int t = blockIdx.x; t < NT; t += gridDim.x) {
        const int bm = t / NBN, bn = t - bm*NBN;

        auto load_stage = [&](int kt) {
            __half* base = sh + (kt % 3)*GSTAGE_HALF;
            #pragma unroll
            for (int p = 0; p < 4; p++) {
                int j = tid + p*256;
                int mbl = j >> 7, kgl = (j >> 5) & 3, ln = j & 31;
                cp16(s2u(base + (size_t)j*8),
                     Ah + (((size_t)(bm*8 + mbl)*KG16 + kt*4 + kgl)*32 + ln)*8);
            }
            __half* bb = base + 8192;
            #pragma unroll
            for (int p = 0; p < 4; p++) {
                int j = tid + p*256;
                int kgl = j >> 8, r = j & 255, nl = r >> 1, hf = r & 1;
                cp16(s2u(bb + (kgl*128 + nl)*16 + hf*8),
                     Wh + ((size_t)(kt*4 + kgl)*N + bn*128 + nl)*16 + hf*8);
            }
            cp_commit();
        };

        float acc[2][8][4];
        #pragma unroll
        for (int mf = 0; mf < 2; mf++)
            #pragma unroll
            for (int nf = 0; nf < 8; nf++)
                #pragma unroll
                for (int i = 0; i < 4; i++) acc[mf][nf][i] = 0.f;

        load_stage(0);
        load_stage(1);

        for (int kt = 0; kt < KT; kt++) {
            if (kt + 2 < KT) cp_wait1(); else cp_wait0();
            __syncthreads();
            if (kt + 2 < KT) load_stage(kt + 2);

            const __half* base = sh + (kt % 3)*GSTAGE_HALF;
            const uint4* a4 = (const uint4*)base;
            const uint2* b2 = (const uint2*)(base + 8192);

            #pragma unroll
            for (int ks = 0; ks < 4; ks++) {
                uint32_t af[2][4];
                #pragma unroll
                for (int mf = 0; mf < 2; mf++) {
                    uint4 av = a4[((wrow*2 + mf)*4 + ks)*32 + lane];
                    af[mf][0] = av.x; af[mf][1] = av.y;
                    af[mf][2] = av.z; af[mf][3] = av.w;
                }
                #pragma unroll
                for (int nf = 0; nf < 8; nf++) {
                    uint2 bv = b2[(ks*128 + wcol*64 + nf*8 + gid)*4 + tig];
                    mma_f16(acc[0][nf], af[0], (const uint32_t*)&bv);
                    mma_f16(acc[1][nf], af[1], (const uint32_t*)&bv);
                }
            }
        }

        if (MODE == 1) {
            #pragma unroll
            for (int mf = 0; mf < 2; mf++) {
                #pragma unroll
                for (int nf = 0; nf < 8; nf++) {
                    int r = bm*128 + wrow*32 + mf*16 + gid;
                    int c = bn*128 + wcol*64 + nf*8 + tig*2;
                    *(float2*)&C[(size_t)r*N + c]
                        = make_float2(acc[mf][nf][0], acc[mf][nf][1]);
                    *(float2*)&C[(size_t)(r+8)*N + c]
                        = make_float2(acc[mf][nf][2], acc[mf][nf][3]);
                }
            }
            __syncthreads();   // before next tile's loads overwrite stages
        } else {
            // ---- staged coalesced epilogue (tile = one head of Q, K or V) ----
            const float qscale = (bn < NHQ) ? 0.08838834764831845f : 1.0f;
            __syncthreads();   // all warps done reading smem stages

            // stage acc as fp16 tile [128][SROW] (banks 4*gid+tig: conflict-free)
            #pragma unroll
            for (int mf = 0; mf < 2; mf++) {
                #pragma unroll
                for (int nf = 0; nf < 8; nf++) {
                    int r0 = wrow*32 + mf*16 + gid;
                    int c  = wcol*64 + nf*8 + tig*2;
                    *(uint32_t*)&sh[r0*SROW + c]
                        = f2h2(acc[mf][nf][0]*qscale, acc[mf][nf][1]*qscale);
                    *(uint32_t*)&sh[(r0+8)*SROW + c]
                        = f2h2(acc[mf][nf][2]*qscale, acc[mf][nf][3]*qscale);
                }
            }
            __syncthreads();

            if (bn < NHQ) {
                // ---- Q: 64 chunks (b,sbl,kk), each 256 halves contiguous ----
                #pragma unroll
                for (int it = 0; it < 8; it++) {
                    int c0 = it*8 + wid;
                    int b = c0 >> 5, sbl = (c0 >> 3) & 3, kk = c0 & 7;
                    int gq = lane >> 2, tq = lane & 3;
                    __half vals[8];
                    #pragma unroll
                    for (int e2 = 0; e2 < 4; e2++) {    // e2 = cs*2 + rs
                        int cs = e2 >> 1, rs = e2 & 1;
                        int r = 2*(sbl*16 + rs*8 + gq) + b;
                        int col = kk*16 + cs*8 + tq*2;
                        ((uint32_t*)vals)[e2] = *(uint32_t*)&sh[r*SROW + col];
                    }
                    size_t bh = (size_t)(b*NHQ + bn);
                    size_t base = (((bh*128 + (bm*4 + sbl))*8 + kk)*32 + lane)*8;
                    *(uint4*)&g_Q2h[base] = *(uint4*)vals;
                }
            } else if (bn < NHQ + NKV) {
                // ---- K: warp = ds; rows -> (b,s); 32B contiguous per row ----
                const int ds = wid, hk = bn - NHQ;
                #pragma unroll
                for (int i = 0; i < 4; i++) {
                    int r = lane + 32*i;
                    int b = r & 1, s = bm*64 + (r >> 1);
                    __half vals[16];
                    #pragma unroll
                    for (int j = 0; j < 8; j++) {
                        int t2 = (j < 4) ? 2*j : 2*(j-4) + 1;
                        ((uint32_t*)vals)[t2] = *(uint32_t*)&sh[r*SROW + ds*16 + 2*j];
                    }
                    size_t base = (((size_t)(b*NKV + hk)*8 + ds)*S_LEN + s)*16;
                    *(uint4*)&g_K2h[base]     = *(uint4*)&vals[0];
                    *(uint4*)&g_K2h[base + 8] = *(uint4*)&vals[8];
                }
            } else {
                // ---- V: warp = (b,kgl); 32B contiguous per (d) ----
                const int b = wid >> 2, kgl = wid & 3, hk = bn - NHQ - NKV;
                const int kg = bm*4 + kgl;
                const size_t bhk = (size_t)(b*NKV + hk);
                #pragma unroll
                for (int i = 0; i < 4; i++) {
                    int d = i*32 + lane;
                    __half vals[16];
                    #pragma unroll
                    for (int j = 0; j < 8; j++) {
                        int t2 = (j < 4) ? 2*j : 2*(j-4) + 1;
                        int rbase = kgl*32 + 4*j + b;
                        vals[t2*2]     = sh[rbase*SROW + d];         // lo_s = 0
                        vals[t2*2 + 1] = sh[(rbase + 2)*SROW + d];   // lo_s = 1
                    }
                    size_t base = ((bhk*128 + kg)*128 + d)*16;
                    *(uint4*)&g_V2h[base]     = *(uint4*)&vals[0];
                    *(uint4*)&g_V2h[base + 8] = *(uint4*)&vals[8];
                }
            }
            __syncthreads();   // gathers done before next tile's loads
        }
    }
}

// =====================================================================
// fp16 flash attention (unchanged from R6): block=(qtile 128, h, b),
// 8 warps x 16 q-rows, BKV=64, 4-stage cp.async pipeline.
// =====================================================================
#define ASTAGE_HALF 16384
#define ATTN_SMEM (4*ASTAGE_HALF*2)   // 131072 B

__global__ __launch_bounds__(256, 1)
void attn_kernel() {
    extern __shared__ __half sh[];

    const int tid = threadIdx.x;
    const int wid = tid >> 5, lane = tid & 31;
    const int gid = lane >> 2, tig = lane & 3;
    const int qt = blockIdx.x, h = blockIdx.y, b = blockIdx.z;
    const int hk = h >> 2;
    const int bh = b*NHQ + h, bhk = b*NKV + hk;

    const int sb = qt*8 + wid;
    const uint4* q4 = (const uint4*)g_Q2h + ((size_t)bh*128 + sb)*8*32 + lane;
    uint32_t qa[8][4];
    #pragma unroll
    for (int kk = 0; kk < 8; kk++) {
        uint4 qv = q4[kk*32];
        qa[kk][0] = qv.x; qa[kk][1] = qv.y; qa[kk][2] = qv.z; qa[kk][3] = qv.w;
    }

    const __half* Kg = g_K2h + (size_t)bhk*8*S_LEN*16;
    const __half* Vg = g_V2h + (size_t)bhk*128*HDIM*16;

    auto loadKV = [&](int it) {
        __half* kd = sh + (it & 3)*ASTAGE_HALF;
        #pragma unroll
        for (int p = 0; p < 4; p++) {
            int j = tid + p*256;
            int ds = j >> 7, r = j & 127, kvl = r >> 1, hf = r & 1;
            cp16(s2u(kd + (ds*64 + kvl)*16 + hf*8),
                 Kg + ((size_t)ds*S_LEN + it*64 + kvl)*16 + hf*8);
        }
        __half* vd = kd + 8192;
        #pragma unroll
        for (int p = 0; p < 4; p++) {
            int j = tid + p*256;
            int kg = j >> 8, r = j & 255, d = r >> 1, hf = r & 1;
            cp16(s2u(vd + (kg*128 + d)*16 + hf*8),
                 Vg + ((size_t)(it*4 + kg)*HDIM + d)*16 + hf*8);
        }
        cp_commit();
    };

    float m0 = NEG_INF, m1 = NEG_INF, l0 = 0.f, l1 = 0.f;
    float o[16][4];
    #pragma unroll
    for (int jn = 0; jn < 16; jn++)
        #pragma unroll
        for (int i = 0; i < 4; i++) o[jn][i] = 0.f;

    loadKV(0); loadKV(1); loadKV(2);

    const int NIT = S_LEN / 64;   // 32
    for (int it = 0; it < NIT; it++) {
        if (it + 3 < NIT) cp_wait2(); else cp_wait0();
        __syncthreads();
        if (it + 3 < NIT) loadKV(it + 3);

        const __half* base = sh + (it & 3)*ASTAGE_HALF;
        const uint2* kb = (const uint2*)base;
        const uint2* vb = (const uint2*)(base + 8192);

        float sc[8][4];
        #pragma unroll
        for (int jn = 0; jn < 8; jn++)
            #pragma unroll
            for (int i = 0; i < 4; i++) sc[jn][i] = 0.f;

        #pragma unroll
        for (int ks = 0; ks < 8; ks++) {
            #pragma unroll
            for (int jn = 0; jn < 8; jn++) {
                uint2 kv = kb[(ks*64 + jn*8 + gid)*4 + tig];
                mma_f16(sc[jn], qa[ks], (const uint32_t*)&kv);
            }
        }

        float rmax0 = NEG_INF, rmax1 = NEG_INF;
        #pragma unroll
        for (int jn = 0; jn < 8; jn++) {
            rmax0 = fmaxf(rmax0, fmaxf(sc[jn][0], sc[jn][1]));
            rmax1 = fmaxf(rmax1, fmaxf(sc[jn][2], sc[jn][3]));
        }
        rmax0 = fmaxf(rmax0, __shfl_xor_sync(0xffffffffu, rmax0, 1));
        rmax0 = fmaxf(rmax0, __shfl_xor_sync(0xffffffffu, rmax0, 2));
        rmax1 = fmaxf(rmax1, __shfl_xor_sync(0xffffffffu, rmax1, 1));
        rmax1 = fmaxf(rmax1, __shfl_xor_sync(0xffffffffu, rmax1, 2));

        float mn0 = fmaxf(m0, rmax0), mn1 = fmaxf(m1, rmax1);
        float al0 = __expf(m0 - mn0), al1 = __expf(m1 - mn1);

        float rs0 = 0.f, rs1 = 0.f;
        #pragma unroll
        for (int jn = 0; jn < 8; jn++) {
            sc[jn][0] = __expf(sc[jn][0] - mn0);
            sc[jn][1] = __expf(sc[jn][1] - mn0);
            sc[jn][2] = __expf(sc[jn][2] - mn1);
            sc[jn][3] = __expf(sc[jn][3] - mn1);
            rs0 += sc[jn][0] + sc[jn][1];
            rs1 += sc[jn][2] + sc[jn][3];
        }
        rs0 += __shfl_xor_sync(0xffffffffu, rs0, 1);
        rs0 += __shfl_xor_sync(0xffffffffu, rs0, 2);
        rs1 += __shfl_xor_sync(0xffffffffu, rs1, 1);
        rs1 += __shfl_xor_sync(0xffffffffu, rs1, 2);

        l0 = l0*al0 + rs0;  l1 = l1*al1 + rs1;
        m0 = mn0;           m1 = mn1;

        #pragma unroll
        for (int jn = 0; jn < 16; jn++) {
            o[jn][0] *= al0; o[jn][1] *= al0;
            o[jn][2] *= al1; o[jn][3] *= al1;
        }

        #pragma unroll
        for (int g = 0; g < 4; g++) {
            uint32_t pa[4];
            pa[0] = f2h2(sc[2*g  ][0], sc[2*g  ][1]);
            pa[1] = f2h2(sc[2*g  ][2], sc[2*g  ][3]);
            pa[2] = f2h2(sc[2*g+1][0], sc[2*g+1][1]);
            pa[3] = f2h2(sc[2*g+1][2], sc[2*g+1][3]);
            #pragma unroll
            for (int jn = 0; jn < 16; jn++) {
                uint2 vv = vb[(g*128 + jn*8 + gid)*4 + tig];
                mma_f16(o[jn], pa, (const uint32_t*)&vv);
            }
        }
    }

    // ---- epilogue: fp16 A-fragment scatter into g_attn2h ----
    float il0 = 1.f / l0, il1 = 1.f / l1;
    const int s0 = qt*128 + wid*16 + gid;
    #pragma unroll
    for (int jn = 0; jn < 16; jn++) {
        int c0 = h*HDIM + jn*8 + tig*2;
        float vals[4] = { o[jn][0]*il0, o[jn][1]*il0, o[jn][2]*il1, o[jn][3]*il1 };
        #pragma unroll
        for (int i = 0; i < 4; i++) {
            int s = s0 + (i >> 1)*8;
            int k = c0 + (i & 1);
            int m = 2*s + b;
            int mb = m >> 4, ml = m & 15, gA = ml & 7, rsA = ml >> 3;
            int kg = k >> 4, kl = k & 15, csA = kl >> 3, tA = (kl & 7) >> 1, loA = k & 1;
            g_attn2h[(((size_t)mb*KG16 + kg)*32 + gA*4 + tA)*8 + (rsA + 2*csA)*2 + loA]
                = __float2half_rn(vals[i]);
        }
    }
}

// =====================================================================
// launcher
// =====================================================================
extern "C" void kernel_launch(void* const* d_in, const int* in_sizes, int n_in,
                              void* d_out, int out_size) {
    const float* hidden = (const float*)d_in[0];
    const float* w_qkv  = (const float*)d_in[1];
    const float* w_o    = (const float*)d_in[2];
    float* out = (float*)d_out;

    cudaFuncSetAttribute(gemm_h_kernel<N_QKV,0>,
                         cudaFuncAttributeMaxDynamicSharedMemorySize, GEMM_SMEM);
    cudaFuncSetAttribute(gemm_h_kernel<DMODEL,1>,
                         cudaFuncAttributeMaxDynamicSharedMemorySize, GEMM_SMEM);
    cudaFuncSetAttribute(attn_kernel,
                         cudaFuncAttributeMaxDynamicSharedMemorySize, ATTN_SMEM);

    __half* hid2h;  cudaGetSymbolAddress((void**)&hid2h, g_hid2h);
    __half* wq2h;   cudaGetSymbolAddress((void**)&wq2h,  g_Wq2h);
    __half* wo2h;   cudaGetSymbolAddress((void**)&wo2h,  g_Wo2h);
    __half* at2h;   cudaGetSymbolAddress((void**)&at2h,  g_attn2h);

    // 0) prepasses: fp32 -> fp16 fragment/pair layouts
    pack_A_kernel<<<dim3(16, 256), 256>>>(hidden, hid2h);
    pack_W_kernel<N_QKV><<<dim3(N_QKV/256, KG16), 256>>>(w_qkv, wq2h);
    pack_W_kernel<DMODEL><<<dim3(DMODEL/256, KG16), 256>>>(w_o, wo2h);

    // 1) fused QKV projection (persistent), staged scatter -> Q2h/K2h/V2h
    gemm_h_kernel<N_QKV,0><<<GRID_P, 256, GEMM_SMEM>>>(hid2h, wq2h, nullptr);

    // 2) flash attention (full softmax == ring online-softmax)
    attn_kernel<<<dim3(S_LEN/128, NHQ, BATCH), 256, ATTN_SMEM>>>();

    // 3) output projection (persistent)
    gemm_h_kernel<DMODEL,1><<<GRID_P, 256, GEMM_SMEM>>>(at2h, wo2h, out);
}

// round 8
// speedup vs baseline: 2.1446x; 1.0147x over previous
#include <cuda_runtime.h>
#include <cuda_fp16.h>
#include <cstdint>
#include <cstddef>

// ---------------- problem dims ----------------
#define S_LEN  2048
#define BATCH  2
#define DMODEL 4096
#define NHQ    32
#define NKV    8
#define HDIM   128
#define N_QKV  ((NHQ + 2*NKV)*HDIM)   // 6144
#define MROWS  (S_LEN*BATCH)          // 4096
#define KG16   (DMODEL/16)            // 256
#define NSM    148
#define GRID_P (2*NSM)                // persistent grid (2 CTAs/SM)

// ---------------- scratch (device globals) ----------------
__device__ __half g_hid2h [(size_t)MROWS*DMODEL];
__device__ __half g_attn2h[(size_t)MROWS*DMODEL];
__device__ __half g_Wq2h[(size_t)DMODEL*N_QKV];
__device__ __half g_Wo2h[(size_t)DMODEL*DMODEL];
// Q A-frag layout: (((bh*128+sb)*8 + kk)*32 + lane)*8 + (rs+2cs)*2 + lo
__device__ __half g_Q2h[(size_t)BATCH*NHQ*S_LEN*HDIM];
// K pair layout (pairs over d):  ((bhk*8+ds)*2048 + s)*16 + t2*2 + lo
__device__ __half g_K2h[(size_t)BATCH*NKV*S_LEN*HDIM];
// V pair layout (pairs over s):  ((bhk*128+kg)*128 + d)*16 + t2*2 + lo
__device__ __half g_V2h[(size_t)BATCH*NKV*S_LEN*HDIM];

// ---------------- helpers ----------------
__device__ __forceinline__ uint32_t f2h2(float lo, float hi) {
    __half2 h = __floats2half2_rn(lo, hi);   // .x = lo half
    return *reinterpret_cast<uint32_t*>(&h);
}
__device__ __forceinline__ void mma_f16(float* c, const uint32_t* a, const uint32_t* b) {
    asm volatile(
        "mma.sync.aligned.m16n8k16.row.col.f32.f16.f16.f32 "
        "{%0,%1,%2,%3},{%4,%5,%6,%7},{%8,%9},{%0,%1,%2,%3};"
        : "+f"(c[0]), "+f"(c[1]), "+f"(c[2]), "+f"(c[3])
        : "r"(a[0]), "r"(a[1]), "r"(a[2]), "r"(a[3]), "r"(b[0]), "r"(b[1]));
}
__device__ __forceinline__ uint32_t s2u(const void* p) {
    return (uint32_t)__cvta_generic_to_shared(p);
}
__device__ __forceinline__ void cp16(uint32_t s, const void* g) {
    asm volatile("cp.async.cg.shared.global [%0], [%1], 16;" :: "r"(s), "l"(g));
}
__device__ __forceinline__ void cp_commit() { asm volatile("cp.async.commit_group;"); }
__device__ __forceinline__ void cp_wait0() { asm volatile("cp.async.wait_group 0;"); }
__device__ __forceinline__ void cp_wait1() { asm volatile("cp.async.wait_group 1;"); }
__device__ __forceinline__ void cp_wait2() { asm volatile("cp.async.wait_group 2;"); }

#define NEG_INF __int_as_float(0xff800000)

// =====================================================================
// Prepass 1: hidden [4096 x 4096] fp32 -> A-fragment fp16 layout
// =====================================================================
__global__ __launch_bounds__(256) void pack_A_kernel(const float* __restrict__ src,
                                                     __half* __restrict__ dst) {
    __shared__ float st[16][264];
    const int tid = threadIdx.x;
    const int mb = blockIdx.y;
    const int k0 = blockIdx.x * 256;
    #pragma unroll
    for (int p = 0; p < 16; p++) {
        int j = tid + p*256;
        int row = j >> 8, col = j & 255;
        st[row][col] = src[(size_t)(mb*16 + row)*DMODEL + k0 + col];
    }
    __syncthreads();
    const int kgb = k0 >> 4;
    #pragma unroll
    for (int p = 0; p < 2; p++) {
        int jb = tid + p*256;
        int kg_l = jb >> 5, lane = jb & 31;
        int gid = lane >> 2, tq = lane & 3;
        int c0 = kg_l*16 + 2*tq;
        int c1 = c0 + 8;
        uint4 o;
        o.x = f2h2(st[gid    ][c0], st[gid    ][c0+1]);
        o.y = f2h2(st[gid + 8][c0], st[gid + 8][c0+1]);
        o.z = f2h2(st[gid    ][c1], st[gid    ][c1+1]);
        o.w = f2h2(st[gid + 8][c1], st[gid + 8][c1+1]);
        *(uint4*)(dst + (((size_t)mb*KG16 + kgb + kg_l)*32 + lane)*8) = o;
    }
}

// =====================================================================
// Prepass 2: W [4096 x N] fp32 -> pair fp16 layout [kg16][n][16]
// =====================================================================
template<int N>
__global__ __launch_bounds__(256) void pack_W_kernel(const float* __restrict__ src,
                                                     __half* __restrict__ dst) {
    __shared__ float st[16][264];
    const int tid = threadIdx.x;
    const int kg = blockIdx.y;
    const int n0 = blockIdx.x * 256;
    #pragma unroll
    for (int p = 0; p < 16; p++)
        st[p][tid] = src[(size_t)(kg*16 + p)*N + n0 + tid];
    __syncthreads();
    const int n = n0 + tid;
    uint32_t h2s[8];
    #pragma unroll
    for (int j = 0; j < 8; j++) {
        int t2 = (j < 4) ? 2*j : 2*(j-4) + 1;
        h2s[t2] = f2h2(st[2*j][tid], st[2*j+1][tid]);
    }
    uint4* d = (uint4*)(dst + ((size_t)kg*N + n)*16);
    d[0] = make_uint4(h2s[0], h2s[1], h2s[2], h2s[3]);
    d[1] = make_uint4(h2s[4], h2s[5], h2s[6], h2s[7]);
}

// =====================================================================
// fp16 GEMM, persistent 128-thread CTAs (4 warps, 2x2), CTA tile 128x128,
// warp tile 64x64 (128 B smem / MMA), BK=64, 3-stage cp.async, 2 CTAs/SM.
// MODE 0: smem-staged coalesced scatter -> Q2h/K2h/V2h
// MODE 1: fp32 row-major C
// =====================================================================
#define GSTAGE_HALF 16384                 // 32 KB per stage
#define GEMM_SMEM (3*GSTAGE_HALF*2)       // 98304 B
#define SROW 136                          // staging row stride in halves

template<int N, int MODE>
__global__ __launch_bounds__(128, 2)
void gemm_h_kernel(const __half* __restrict__ Ah,
                   const __half* __restrict__ Wh,
                   float* __restrict__ C) {
    constexpr int KT  = DMODEL / 64;     // 64
    constexpr int NBN = N / 128;
    constexpr int NT  = (MROWS/128) * NBN;

    extern __shared__ __half sh[];

    const int tid  = threadIdx.x;
    const int wid  = tid >> 5, lane = tid & 31;
    const int gid  = lane >> 2, tig = lane & 3;
    const int wrow = wid >> 1, wcol = wid & 1;   // warp grid 2(M) x 2(N)

    for (int t = blockIdx.x; t < NT; t += gridDim.x) {
        const int bm = t / NBN, bn = t - bm*NBN;

        auto load_stage = [&](int kt) {
            __half* base = sh + (kt % 3)*GSTAGE_HALF;
            #pragma unroll
            for (int p = 0; p < 8; p++) {            // A: 1024 chunks
                int j = tid + p*128;
                int mbl = j >> 7, kgl = (j >> 5) & 3, ln = j & 31;
                cp16(s2u(base + (size_t)j*8),
                     Ah + (((size_t)(bm*8 + mbl)*KG16 + kt*4 + kgl)*32 + ln)*8);
            }
            __half* bb = base + 8192;
            #pragma unroll
            for (int p = 0; p < 8; p++) {            // B: 1024 chunks
                int j = tid + p*128;
                int kgl = j >> 8, r = j & 255, nl = r >> 1, hf = r & 1;
                cp16(s2u(bb + (kgl*128 + nl)*16 + hf*8),
                     Wh + ((size_t)(kt*4 + kgl)*N + bn*128 + nl)*16 + hf*8);
            }
            cp_commit();
        };

        float acc[4][8][4];
        #pragma unroll
        for (int mf = 0; mf < 4; mf++)
            #pragma unroll
            for (int nf = 0; nf < 8; nf++)
                #pragma unroll
                for (int i = 0; i < 4; i++) acc[mf][nf][i] = 0.f;

        load_stage(0);
        load_stage(1);

        for (int kt = 0; kt < KT; kt++) {
            if (kt + 2 < KT) cp_wait1(); else cp_wait0();
            __syncthreads();
            if (kt + 2 < KT) load_stage(kt + 2);

            const __half* base = sh + (kt % 3)*GSTAGE_HALF;
            const uint4* a4 = (const uint4*)base;
            const uint2* b2 = (const uint2*)(base + 8192);

            #pragma unroll
            for (int ks = 0; ks < 4; ks++) {
                uint32_t af[4][4];
                #pragma unroll
                for (int mf = 0; mf < 4; mf++) {
                    uint4 av = a4[((wrow*4 + mf)*4 + ks)*32 + lane];
                    af[mf][0] = av.x; af[mf][1] = av.y;
                    af[mf][2] = av.z; af[mf][3] = av.w;
                }
                #pragma unroll
                for (int nf = 0; nf < 8; nf++) {
                    uint2 bv = b2[(ks*128 + wcol*64 + nf*8 + gid)*4 + tig];
                    #pragma unroll
                    for (int mf = 0; mf < 4; mf++)
                        mma_f16(acc[mf][nf], af[mf], (const uint32_t*)&bv);
                }
            }
        }

        if (MODE == 1) {
            #pragma unroll
            for (int mf = 0; mf < 4; mf++) {
                #pragma unroll
                for (int nf = 0; nf < 8; nf++) {
                    int r = bm*128 + wrow*64 + mf*16 + gid;
                    int c = bn*128 + wcol*64 + nf*8 + tig*2;
                    *(float2*)&C[(size_t)r*N + c]
                        = make_float2(acc[mf][nf][0], acc[mf][nf][1]);
                    *(float2*)&C[(size_t)(r+8)*N + c]
                        = make_float2(acc[mf][nf][2], acc[mf][nf][3]);
                }
            }
            __syncthreads();   // before next tile's loads overwrite stages
        } else {
            // ---- staged coalesced epilogue (tile = one head of Q, K or V) ----
            const float qscale = (bn < NHQ) ? 0.08838834764831845f : 1.0f;
            __syncthreads();   // all warps done reading smem stages

            // stage acc as fp16 tile [128][SROW] (banks conflict-free per warp)
            #pragma unroll
            for (int mf = 0; mf < 4; mf++) {
                #pragma unroll
                for (int nf = 0; nf < 8; nf++) {
                    int r0 = wrow*64 + mf*16 + gid;
                    int c  = wcol*64 + nf*8 + tig*2;
                    *(uint32_t*)&sh[r0*SROW + c]
                        = f2h2(acc[mf][nf][0]*qscale, acc[mf][nf][1]*qscale);
                    *(uint32_t*)&sh[(r0+8)*SROW + c]
                        = f2h2(acc[mf][nf][2]*qscale, acc[mf][nf][3]*qscale);
                }
            }
            __syncthreads();

            if (bn < NHQ) {
                // ---- Q: 64 chunks (b,sbl,kk), 4 warps x 16 iters ----
                #pragma unroll
                for (int it = 0; it < 16; it++) {
                    int c0 = it*4 + wid;
                    int b = c0 >> 5, sbl = (c0 >> 3) & 3, kk = c0 & 7;
                    int gq = lane >> 2, tq = lane & 3;
                    __half vals[8];
                    #pragma unroll
                    for (int e2 = 0; e2 < 4; e2++) {    // e2 = cs*2 + rs
                        int cs = e2 >> 1, rs = e2 & 1;
                        int r = 2*(sbl*16 + rs*8 + gq) + b;
                        int col = kk*16 + cs*8 + tq*2;
                        ((uint32_t*)vals)[e2] = *(uint32_t*)&sh[r*SROW + col];
                    }
                    size_t bh = (size_t)(b*NHQ + bn);
                    size_t base = (((bh*128 + (bm*4 + sbl))*8 + kk)*32 + lane)*8;
                    *(uint4*)&g_Q2h[base] = *(uint4*)vals;
                }
            } else if (bn < NHQ + NKV) {
                // ---- K: ds 0..7 over 4 warps x 2 rounds ----
                const int hk = bn - NHQ;
                #pragma unroll
                for (int dsi = 0; dsi < 2; dsi++) {
                    int ds = dsi*4 + wid;
                    #pragma unroll
                    for (int i = 0; i < 4; i++) {
                        int r = lane + 32*i;
                        int b = r & 1, s = bm*64 + (r >> 1);
                        __half vals[16];
                        #pragma unroll
                        for (int j = 0; j < 8; j++) {
                            int t2 = (j < 4) ? 2*j : 2*(j-4) + 1;
                            ((uint32_t*)vals)[t2] = *(uint32_t*)&sh[r*SROW + ds*16 + 2*j];
                        }
                        size_t base = (((size_t)(b*NKV + hk)*8 + ds)*S_LEN + s)*16;
                        *(uint4*)&g_K2h[base]     = *(uint4*)&vals[0];
                        *(uint4*)&g_K2h[base + 8] = *(uint4*)&vals[8];
                    }
                }
            } else {
                // ---- V: (b,kgl) 8 combos over 4 warps x 2 rounds ----
                const int hk = bn - NHQ - NKV;
                #pragma unroll
                for (int vi = 0; vi < 2; vi++) {
                    int w2 = vi*4 + wid;
                    int b = w2 >> 2, kgl = w2 & 3;
                    int kg = bm*4 + kgl;
                    size_t bhk = (size_t)(b*NKV + hk);
                    #pragma unroll
                    for (int i = 0; i < 4; i++) {
                        int d = i*32 + lane;
                        __half vals[16];
                        #pragma unroll
                        for (int j = 0; j < 8; j++) {
                            int t2 = (j < 4) ? 2*j : 2*(j-4) + 1;
                            int rbase = kgl*32 + 4*j + b;
                            vals[t2*2]     = sh[rbase*SROW + d];
                            vals[t2*2 + 1] = sh[(rbase + 2)*SROW + d];
                        }
                        size_t base = ((bhk*128 + kg)*128 + d)*16;
                        *(uint4*)&g_V2h[base]     = *(uint4*)&vals[0];
                        *(uint4*)&g_V2h[base + 8] = *(uint4*)&vals[8];
                    }
                }
            }
            __syncthreads();   // gathers done before next tile's loads
        }
    }
}

// =====================================================================
// fp16 flash attention (unchanged): block=(qtile 128, h, b),
// 8 warps x 16 q-rows, BKV=64, 4-stage cp.async pipeline.
// =====================================================================
#define ASTAGE_HALF 16384
#define ATTN_SMEM (4*ASTAGE_HALF*2)   // 131072 B

__global__ __launch_bounds__(256, 1)
void attn_kernel() {
    extern __shared__ __half sh[];

    const int tid = threadIdx.x;
    const int wid = tid >> 5, lane = tid & 31;
    const int gid = lane >> 2, tig = lane & 3;
    const int qt = blockIdx.x, h = blockIdx.y, b = blockIdx.z;
    const int hk = h >> 2;
    const int bh = b*NHQ + h, bhk = b*NKV + hk;

    const int sb = qt*8 + wid;
    const uint4* q4 = (const uint4*)g_Q2h + ((size_t)bh*128 + sb)*8*32 + lane;
    uint32_t qa[8][4];
    #pragma unroll
    for (int kk = 0; kk < 8; kk++) {
        uint4 qv = q4[kk*32];
        qa[kk][0] = qv.x; qa[kk][1] = qv.y; qa[kk][2] = qv.z; qa[kk][3] = qv.w;
    }

    const __half* Kg = g_K2h + (size_t)bhk*8*S_LEN*16;
    const __half* Vg = g_V2h + (size_t)bhk*128*HDIM*16;

    auto loadKV = [&](int it) {
        __half* kd = sh + (it & 3)*ASTAGE_HALF;
        #pragma unroll
        for (int p = 0; p < 4; p++) {
            int j = tid + p*256;
            int ds = j >> 7, r = j & 127, kvl = r >> 1, hf = r & 1;
            cp16(s2u(kd + (ds*64 + kvl)*16 + hf*8),
                 Kg + ((size_t)ds*S_LEN + it*64 + kvl)*16 + hf*8);
        }
        __half* vd = kd + 8192;
        #pragma unroll
        for (int p = 0; p < 4; p++) {
            int j = tid + p*256;
            int kg = j >> 8, r = j & 255, d = r >> 1, hf = r & 1;
            cp16(s2u(vd + (kg*128 + d)*16 + hf*8),
                 Vg + ((size_t)(it*4 + kg)*HDIM + d)*16 + hf*8);
        }
        cp_commit();
    };

    float m0 = NEG_INF, m1 = NEG_INF, l0 = 0.f, l1 = 0.f;
    float o[16][4];
    #pragma unroll
    for (int jn = 0; jn < 16; jn++)
        #pragma unroll
        for (int i = 0; i < 4; i++) o[jn][i] = 0.f;

    loadKV(0); loadKV(1); loadKV(2);

    const int NIT = S_LEN / 64;   // 32
    for (int it = 0; it < NIT; it++) {
        if (it + 3 < NIT) cp_wait2(); else cp_wait0();
        __syncthreads();
        if (it + 3 < NIT) loadKV(it + 3);

        const __half* base = sh + (it & 3)*ASTAGE_HALF;
        const uint2* kb = (const uint2*)base;
        const uint2* vb = (const uint2*)(base + 8192);

        float sc[8][4];
        #pragma unroll
        for (int jn = 0; jn < 8; jn++)
            #pragma unroll
            for (int i = 0; i < 4; i++) sc[jn][i] = 0.f;

        #pragma unroll
        for (int ks = 0; ks < 8; ks++) {
            #pragma unroll
            for (int jn = 0; jn < 8; jn++) {
                uint2 kv = kb[(ks*64 + jn*8 + gid)*4 + tig];
                mma_f16(sc[jn], qa[ks], (const uint32_t*)&kv);
            }
        }

        float rmax0 = NEG_INF, rmax1 = NEG_INF;
        #pragma unroll
        for (int jn = 0; jn < 8; jn++) {
            rmax0 = fmaxf(rmax0, fmaxf(sc[jn][0], sc[jn][1]));
            rmax1 = fmaxf(rmax1, fmaxf(sc[jn][2], sc[jn][3]));
        }
        rmax0 = fmaxf(rmax0, __shfl_xor_sync(0xffffffffu, rmax0, 1));
        rmax0 = fmaxf(rmax0, __shfl_xor_sync(0xffffffffu, rmax0, 2));
        rmax1 = fmaxf(rmax1, __shfl_xor_sync(0xffffffffu, rmax1, 1));
        rmax1 = fmaxf(rmax1, __shfl_xor_sync(0xffffffffu, rmax1, 2));

        float mn0 = fmaxf(m0, rmax0), mn1 = fmaxf(m1, rmax1);
        float al0 = __expf(m0 - mn0), al1 = __expf(m1 - mn1);

        float rs0 = 0.f, rs1 = 0.f;
        #pragma unroll
        for (int jn = 0; jn < 8; jn++) {
            sc[jn][0] = __expf(sc[jn][0] - mn0);
            sc[jn][1] = __expf(sc[jn][1] - mn0);
            sc[jn][2] = __expf(sc[jn][2] - mn1);
            sc[jn][3] = __expf(sc[jn][3] - mn1);
            rs0 += sc[jn][0] + sc[jn][1];
            rs1 += sc[jn][2] + sc[jn][3];
        }
        rs0 += __shfl_xor_sync(0xffffffffu, rs0, 1);
        rs0 += __shfl_xor_sync(0xffffffffu, rs0, 2);
        rs1 += __shfl_xor_sync(0xffffffffu, rs1, 1);
        rs1 += __shfl_xor_sync(0xffffffffu, rs1, 2);

        l0 = l0*al0 + rs0;  l1 = l1*al1 + rs1;
        m0 = mn0;           m1 = mn1;

        #pragma unroll
        for (int jn = 0; jn < 16; jn++) {
            o[jn][0] *= al0; o[jn][1] *= al0;
            o[jn][2] *= al1; o[jn][3] *= al1;
        }

        #pragma unroll
        for (int g = 0; g < 4; g++) {
            uint32_t pa[4];
            pa[0] = f2h2(sc[2*g  ][0], sc[2*g  ][1]);
            pa[1] = f2h2(sc[2*g  ][2], sc[2*g  ][3]);
            pa[2] = f2h2(sc[2*g+1][0], sc[2*g+1][1]);
            pa[3] = f2h2(sc[2*g+1][2], sc[2*g+1][3]);
            #pragma unroll
            for (int jn = 0; jn < 16; jn++) {
                uint2 vv = vb[(g*128 + jn*8 + gid)*4 + tig];
                mma_f16(o[jn], pa, (const uint32_t*)&vv);
            }
        }
    }

    // ---- epilogue: fp16 A-fragment scatter into g_attn2h ----
    float il0 = 1.f / l0, il1 = 1.f / l1;
    const int s0 = qt*128 + wid*16 + gid;
    #pragma unroll
    for (int jn = 0; jn < 16; jn++) {
        int c0 = h*HDIM + jn*8 + tig*2;
        float vals[4] = { o[jn][0]*il0, o[jn][1]*il0, o[jn][2]*il1, o[jn][3]*il1 };
        #pragma unroll
        for (int i = 0; i < 4; i++) {
            int s = s0 + (i >> 1)*8;
            int k = c0 + (i & 1);
            int m = 2*s + b;
            int mb = m >> 4, ml = m & 15, gA = ml & 7, rsA = ml >> 3;
            int kg = k >> 4, kl = k & 15, csA = kl >> 3, tA = (kl & 7) >> 1, loA = k & 1;
            g_attn2h[(((size_t)mb*KG16 + kg)*32 + gA*4 + tA)*8 + (rsA + 2*csA)*2 + loA]
                = __float2half_rn(vals[i]);
        }
    }
}

// =====================================================================
// launcher
// =====================================================================
extern "C" void kernel_launch(void* const* d_in, const int* in_sizes, int n_in,
                              void* d_out, int out_size) {
    const float* hidden = (const float*)d_in[0];
    const float* w_qkv  = (const float*)d_in[1];
    const float* w_o    = (const float*)d_in[2];
    float* out = (float*)d_out;

    cudaFuncSetAttribute(gemm_h_kernel<N_QKV,0>,
                         cudaFuncAttributeMaxDynamicSharedMemorySize, GEMM_SMEM);
    cudaFuncSetAttribute(gemm_h_kernel<DMODEL,1>,
                         cudaFuncAttributeMaxDynamicSharedMemorySize, GEMM_SMEM);
    cudaFuncSetAttribute(attn_kernel,
                         cudaFuncAttributeMaxDynamicSharedMemorySize, ATTN_SMEM);

    __half* hid2h;  cudaGetSymbolAddress((void**)&hid2h, g_hid2h);
    __half* wq2h;   cudaGetSymbolAddress((void**)&wq2h,  g_Wq2h);
    __half* wo2h;   cudaGetSymbolAddress((void**)&wo2h,  g_Wo2h);
    __half* at2h;   cudaGetSymbolAddress((void**)&at2h,  g_attn2h);

    // 0) prepasses: fp32 -> fp16 fragment/pair layouts
    pack_A_kernel<<<dim3(16, 256), 256>>>(hidden, hid2h);
    pack_W_kernel<N_QKV><<<dim3(N_QKV/256, KG16), 256>>>(w_qkv, wq2h);
    pack_W_kernel<DMODEL><<<dim3(DMODEL/256, KG16), 256>>>(w_o, wo2h);

    // 1) fused QKV projection (persistent), staged scatter -> Q2h/K2h/V2h
    gemm_h_kernel<N_QKV,0><<<GRID_P, 128, GEMM_SMEM>>>(hid2h, wq2h, nullptr);

    // 2) flash attention (full softmax == ring online-softmax)
    attn_kernel<<<dim3(S_LEN/128, NHQ, BATCH), 256, ATTN_SMEM>>>();

    // 3) output projection (persistent)
    gemm_h_kernel<DMODEL,1><<<GRID_P, 128, GEMM_SMEM>>>(at2h, wo2h, out);
}